// round 17
// baseline (speedup 1.0000x reference)
#include <cuda_runtime.h>
#include <math.h>
#include <stdint.h>

#define SCALE 16
#define R_MAX 4
#define HL 32
#define WL 32
#define HH 512
#define WH 512
#define C_FEAT 128
#define HW (HH * WH)

// prep scratch
__device__ float    g_guide_lr[3 * HL * WL];
__device__ uint32_t g_feat_hl[HL * WL * C_FEAT];  // [spatial][channel]: bf16hi<<16 | bf16lo

// ---------------- dynamic smem layout (bytes) ----------------
#define CSTR4 130
#define QSTR  72
#define OFF_SCAL   0            // floats: ct, st, isx, isy, isr, Rsq
#define OFF_NACT   32
#define OFF_SI     64           // int[64]
#define OFF_DXF    320          // float[64]
#define OFF_DYF    576          // float[64]
#define OFF_F4     2432         // uint4[16][CSTR4]
#define OFF_QH     (OFF_F4 + 16 * CSTR4 * 16)      // 35712
#define OFF_QL     (OFF_QH + 8 * QSTR * 4)         // +2304
#define SMEM_BYTES (OFF_QL + 8 * QSTR * 4)         // 40320 B

static __device__ __forceinline__ uint32_t pack_bf16x2(float w0, float w1) {
    uint32_t r;
    asm("cvt.rn.bf16x2.f32 %0, %1, %2;" : "=r"(r) : "f"(w1), "f"(w0));
    return r;
}

static __device__ __forceinline__ uint32_t f2tf32(float f) {
    uint32_t r;
    asm("cvt.rna.tf32.f32 %0, %1;" : "=r"(r) : "f"(f));
    return r;
}

#define MMA_BF16(d, a0, a1, a2, a3, b0, b1) \
    asm volatile("mma.sync.aligned.m16n8k16.row.col.f32.bf16.bf16.f32 " \
        "{%0,%1,%2,%3}, {%4,%5,%6,%7}, {%8,%9}, {%0,%1,%2,%3};" \
        : "+f"((d)[0]), "+f"((d)[1]), "+f"((d)[2]), "+f"((d)[3]) \
        : "r"(a0), "r"(a1), "r"(a2), "r"(a3), "r"(b0), "r"(b1))

#define MMA_TF32K8(d, a0, a1, a2, a3, b0, b1) \
    asm volatile("mma.sync.aligned.m16n8k8.row.col.f32.tf32.tf32.f32 " \
        "{%0,%1,%2,%3}, {%4,%5,%6,%7}, {%8,%9}, {%0,%1,%2,%3};" \
        : "+f"((d)[0]), "+f"((d)[1]), "+f"((d)[2]), "+f"((d)[3]) \
        : "r"(a0), "r"(a1), "r"(a2), "r"(a3), "r"(b0), "r"(b1))

// ---------------------------------------------------------------------------
// Prep: bf16 hi/lo split of feat (channel-minor, packed); bilinear-downsample
// guide (separable, rows then columns, matching the reference).
// ---------------------------------------------------------------------------
__global__ void jbu_prep_kernel(const float* __restrict__ feat,
                                const float* __restrict__ guide) {
    int idx = blockIdx.x * blockDim.x + threadIdx.x;

    if (idx < HL * WL * C_FEAT) {
        int c = idx & (C_FEAT - 1);
        int s = idx >> 7;
        float f = feat[c * (HL * WL) + s];
        uint32_t hi2 = pack_bf16x2(f, 0.0f);          // low 16 bits = bf16(f)
        uint32_t hi16 = hi2 & 0xffffu;
        float hif = __uint_as_float(hi16 << 16);
        uint32_t lo2 = pack_bf16x2(f - hif, 0.0f);
        g_feat_hl[idx] = (hi16 << 16) | (lo2 & 0xffffu);
    }
    if (idx < 3 * HL * WL) {
        int c = idx >> 10;
        int rem = idx & 1023;
        int i = rem >> 5;
        int j = rem & 31;

        float srcy = fmaxf((i + 0.5f) * ((float)HH / HL) - 0.5f, 0.0f);
        int r0 = (int)floorf(srcy);
        float tr = srcy - (float)r0;
        int r0c = min(max(r0, 0), HH - 1);
        int r1c = min(max(r0 + 1, 0), HH - 1);

        float srcx = fmaxf((j + 0.5f) * ((float)WH / WL) - 0.5f, 0.0f);
        int c0 = (int)floorf(srcx);
        float tc = srcx - (float)c0;
        int c0c = min(max(c0, 0), WH - 1);
        int c1c = min(max(c0 + 1, 0), WH - 1);

        const float* g = guide + c * HW;
        float v0 = g[r0c * WH + c0c] * (1.0f - tr) + g[r1c * WH + c0c] * tr;
        float v1 = g[r0c * WH + c1c] * (1.0f - tr) + g[r1c * WH + c1c] * tr;
        g_guide_lr[idx] = v0 * (1.0f - tc) + v1 * tc;
    }
}

// ---------------------------------------------------------------------------
// Main: one block per HALF LR cell (8 HR rows x 16 cols x 128 ch).
// Pixel mapping: MMA row r -> x = 2*(r&7) + (r>>3) -> float2 stores.
// lw via split-tf32 m16n8k8 MMA (C seeded with P); main GEMM bf16 hh+lh+hl.
// F-build uses prepacked hi/lo (PRMT only); 2b double-buffers B fragments.
// ---------------------------------------------------------------------------
__global__ __launch_bounds__(128, 5)
void jbu_main_kernel(const float* __restrict__ guide,
                     const float* __restrict__ sx_raw,
                     const float* __restrict__ sy_raw,
                     const float* __restrict__ th_raw,
                     const float* __restrict__ sr_raw,
                     float* __restrict__ out) {
    extern __shared__ __align__(16) char smem[];

    float*    s_scal = (float*)(smem + OFF_SCAL);
    int*      s_nactp = (int*)(smem + OFF_NACT);
    int*      s_si   = (int*)(smem + OFF_SI);
    float*    s_dxf  = (float*)(smem + OFF_DXF);
    float*    s_dyf  = (float*)(smem + OFF_DYF);
    uint4*    F4     = (uint4*)(smem + OFF_F4);
    uint32_t* Qh     = (uint32_t*)(smem + OFF_QH);
    uint32_t* Ql     = (uint32_t*)(smem + OFF_QL);

    const int uc = blockIdx.y;
    const int vc = blockIdx.x;
    const int zh = blockIdx.z;
    const int tid = threadIdx.x;
    const int wid = tid >> 5;
    const int lane = tid & 31;

    // ---- phase 0: params + offset compaction (warp 0, ballot-based) ----
    if (wid == 0) {
        if (lane == 0) {
            int cell = uc * WL + vc;
            float sx = fmaxf(expf(sx_raw[cell]), 1e-6f);
            float sy = fmaxf(expf(sy_raw[cell]), 1e-6f);
            float th = 3.14159265358979323846f * tanhf(th_raw[cell]);
            float sr = fmaxf(expf(sr_raw[cell]), 1e-6f);
            float rr = fminf(fmaxf(2.0f * fmaxf(sx, sy), 1.0f), (float)R_MAX);
            s_scal[0] = cosf(th);
            s_scal[1] = sinf(th);
            s_scal[2] = 1.0f / (2.0f * sx * sx + 1e-8f);
            s_scal[3] = 1.0f / (2.0f * sy * sy + 1e-8f);
            s_scal[4] = 1.0f / (2.0f * sr * sr + 1e-8f);
            s_scal[5] = rr * rr;
        }
        __syncwarp();
        const float Rsq = s_scal[5];
        int base = 0;
#pragma unroll
        for (int chnk = 0; chnk < 3; chnk++) {
            int i = chnk * 32 + lane;
            int dy = i / 9 - R_MAX;
            int dx = i - (i / 9) * 9 - R_MAX;
            bool act = (i < 81) && ((float)(dy * dy + dx * dx) <= Rsq);
            unsigned m = __ballot_sync(0xffffffffu, act);
            int pos = base + __popc(m & ((1u << lane) - 1u));
            if (act) {
                int ui = min(max(uc + dy, 0), HL - 1);
                int vi = min(max(vc + dx, 0), WL - 1);
                s_dyf[pos] = (float)(uc - ui);
                s_dxf[pos] = (float)(vc - vi);
                s_si[pos]  = ui * WL + vi;
            }
            base += __popc(m);
        }
        if (lane == 0) *s_nactp = base;
    }
    __syncthreads();

    const int nact = *s_nactp;                 // <= 49
    const int ksteps = (nact + 15) >> 4;       // <= 4
    const float ct  = s_scal[0];
    const float st  = s_scal[1];
    const float isx = s_scal[2];
    const float isy = s_scal[3];
    const float isr = s_scal[4];

    // ---- build Q (lw coefficient matrix): threads 0..63, one offset each ----
    if (tid < 64) {
        float q[6];
        if (tid < nact) {
            int si = s_si[tid];
            float fdx = s_dxf[tid];
            float fdy = s_dyf[tid];
            float gl0 = g_guide_lr[si];
            float gl1 = g_guide_lr[HL * WL + si];
            float gl2 = g_guide_lr[2 * HL * WL + si];
            float A = fdx * ct + fdy * st;
            float B = fdy * ct - fdx * st;
            float D = (gl0 * gl0 + gl1 * gl1 + gl2 * gl2) * isr;
            q[0] = -2.0f * A * isx;
            q[1] = -2.0f * B * isy;
            q[2] = 2.0f * gl0 * isr;
            q[3] = 2.0f * gl1 * isr;
            q[4] = 2.0f * gl2 * isr;
            q[5] = -(A * A * isx + B * B * isy + D);
        } else {
            q[0] = q[1] = q[2] = q[3] = q[4] = 0.0f;
            q[5] = -1e30f;   // lw -> -1e30 -> w = 0
        }
#pragma unroll
        for (int r = 0; r < 6; r++) {
            uint32_t h = f2tf32(q[r]);
            Qh[r * QSTR + tid] = h;
            Ql[r * QSTR + tid] = f2tf32(q[r] - __uint_as_float(h));
        }
        Qh[6 * QSTR + tid] = 0u; Qh[7 * QSTR + tid] = 0u;
        Ql[6 * QSTR + tid] = 0u; Ql[7 * QSTR + tid] = 0u;
    }
    __syncthreads();

    // ---- phase 1: build F4 via PRMT from prepacked hi/lo ----
    {
        const int nent = ksteps * 4 * C_FEAT;
        for (int e = tid; e < nent; e += 128) {
            int c = e & 127;
            int q = e >> 7;                // ks*4 + lr_b
            int kp0 = (q >> 2) * 8 + (q & 3);
            int kp1 = kp0 + 4;
            int k00 = 2 * kp0, k01 = k00 + 1;
            int k10 = 2 * kp1, k11 = k10 + 1;
            uint32_t w00 = (k00 < nact) ? g_feat_hl[s_si[k00] * C_FEAT + c] : 0u;
            uint32_t w01 = (k01 < nact) ? g_feat_hl[s_si[k01] * C_FEAT + c] : 0u;
            uint32_t w10 = (k10 < nact) ? g_feat_hl[s_si[k10] * C_FEAT + c] : 0u;
            uint32_t w11 = (k11 < nact) ? g_feat_hl[s_si[k11] * C_FEAT + c] : 0u;
            uint32_t hi0 = __byte_perm(w00, w01, 0x7632);  // {bf16hi(f01), bf16hi(f00)}
            uint32_t lo0 = __byte_perm(w00, w01, 0x5410);
            uint32_t hi1 = __byte_perm(w10, w11, 0x7632);
            uint32_t lo1 = __byte_perm(w10, w11, 0x5410);
            F4[q * CSTR4 + c] = make_uint4(hi0, hi1, lo0, lo1);
        }
    }

    const int lq = lane >> 2;         // 0..7
    const int lr = lane & 3;          // 0..3
    const int x0 = vc * SCALE + 2 * lq;

    // ---- phase 2a: lw via split-tf32 MMA, exp, pack to bf16 A-fragments ----
    uint32_t ah[2][4][4], al[2][4][4];
    float inv[2][2];
    uint32_t aw_h[2][4], aw_l[2][4];
    float P[2][2];
    {
        const float px0 = ((float)(2 * lq) - 7.5f) * (1.0f / SCALE);
        const float px1 = ((float)(2 * lq + 1) - 7.5f) * (1.0f / SCALE);
#pragma unroll
        for (int mt = 0; mt < 2; mt++) {
            const int tyc = zh * 8 + 2 * wid + mt;
            const int y = uc * SCALE + tyc;
            const float* gp0 = guide + (size_t)y * WH + x0;
            float2 g01_0 = *(const float2*)(gp0);
            float2 g01_1 = *(const float2*)(gp0 + HW);
            float2 g01_2 = *(const float2*)(gp0 + 2 * HW);
            const float ga0 = g01_0.x, ga1 = g01_1.x, ga2 = g01_2.x;
            const float gb0 = g01_0.y, gb1 = g01_1.y, gb2 = g01_2.y;
            const float py = ((float)tyc - 7.5f) * (1.0f / SCALE);
            const float pa0 = px0 * ct + py * st;
            const float pb0 = py * ct - px0 * st;
            const float pa1 = px1 * ct + py * st;
            const float pb1 = py * ct - px1 * st;

            P[mt][0] = -(pa0 * pa0 * isx + pb0 * pb0 * isy)
                       - (ga0 * ga0 + ga1 * ga1 + ga2 * ga2) * isr;
            P[mt][1] = -(pa1 * pa1 * isx + pb1 * pb1 * isy)
                       - (gb0 * gb0 + gb1 * gb1 + gb2 * gb2) * isr;

            float v0p0 = (lr == 0) ? pa0 : (lr == 1) ? pb0 : (lr == 2) ? ga0 : ga1;
            float v0p1 = (lr == 0) ? pa1 : (lr == 1) ? pb1 : (lr == 2) ? gb0 : gb1;
            float v4p0 = (lr == 0) ? ga2 : (lr == 1) ? 1.0f : 0.0f;
            float v4p1 = (lr == 0) ? gb2 : (lr == 1) ? 1.0f : 0.0f;

            uint32_t h;
            h = f2tf32(v0p0); aw_h[mt][0] = h; aw_l[mt][0] = f2tf32(v0p0 - __uint_as_float(h));
            h = f2tf32(v0p1); aw_h[mt][1] = h; aw_l[mt][1] = f2tf32(v0p1 - __uint_as_float(h));
            h = f2tf32(v4p0); aw_h[mt][2] = h; aw_l[mt][2] = f2tf32(v4p0 - __uint_as_float(h));
            h = f2tf32(v4p1); aw_h[mt][3] = h; aw_l[mt][3] = f2tf32(v4p1 - __uint_as_float(h));
        }
    }

    float den[2][2] = {{0.f, 0.f}, {0.f, 0.f}};
#pragma unroll
    for (int ks = 0; ks < 4; ks++) {
        if (ks >= ksteps) {
#pragma unroll
            for (int mt = 0; mt < 2; mt++)
#pragma unroll
                for (int j = 0; j < 4; j++) { ah[mt][ks][j] = 0u; al[mt][ks][j] = 0u; }
            continue;
        }
#pragma unroll
        for (int j = 0; j < 2; j++) {
            const int nt = 2 * ks + j;
            const int qoff = nt * 8 + lq;
            uint32_t b0h = Qh[lr * QSTR + qoff];
            uint32_t b1h = Qh[(lr + 4) * QSTR + qoff];
            uint32_t b0l = Ql[lr * QSTR + qoff];
            uint32_t b1l = Ql[(lr + 4) * QSTR + qoff];
#pragma unroll
            for (int mt = 0; mt < 2; mt++) {
                float d[4] = {P[mt][0], P[mt][0], P[mt][1], P[mt][1]};
                MMA_TF32K8(d, aw_h[mt][0], aw_h[mt][1], aw_h[mt][2], aw_h[mt][3], b0h, b1h);
                MMA_TF32K8(d, aw_l[mt][0], aw_l[mt][1], aw_l[mt][2], aw_l[mt][3], b0h, b1h);
                MMA_TF32K8(d, aw_h[mt][0], aw_h[mt][1], aw_h[mt][2], aw_h[mt][3], b0l, b1l);
                float e0 = __expf(d[0]);
                float e1 = __expf(d[1]);
                float e2 = __expf(d[2]);
                float e3 = __expf(d[3]);
                den[mt][0] += e0 + e1;
                den[mt][1] += e2 + e3;
                uint32_t hA = pack_bf16x2(e0, e1);
                uint32_t hB = pack_bf16x2(e2, e3);
                uint32_t lA = pack_bf16x2(e0 - __uint_as_float(hA << 16),
                                          e1 - __uint_as_float(hA & 0xffff0000u));
                uint32_t lB = pack_bf16x2(e2 - __uint_as_float(hB << 16),
                                          e3 - __uint_as_float(hB & 0xffff0000u));
                ah[mt][ks][2 * j]     = hA;
                ah[mt][ks][2 * j + 1] = hB;
                al[mt][ks][2 * j]     = lA;
                al[mt][ks][2 * j + 1] = lB;
            }
        }
    }

#pragma unroll
    for (int mt = 0; mt < 2; mt++) {
        float d0 = den[mt][0], d1 = den[mt][1];
        d0 += __shfl_xor_sync(0xffffffffu, d0, 1);
        d0 += __shfl_xor_sync(0xffffffffu, d0, 2);
        d1 += __shfl_xor_sync(0xffffffffu, d1, 1);
        d1 += __shfl_xor_sync(0xffffffffu, d1, 2);
        inv[mt][0] = 1.0f / fmaxf(d0, 1e-8f);
        inv[mt][1] = 1.0f / fmaxf(d1, 1e-8f);
    }

    __syncthreads();   // F4 ready

    // ---- phase 2b: 16 channel-pair iterations, double-buffered B ----
    const int ybase = uc * SCALE + zh * 8 + 2 * wid;
    float* ob0 = out + (size_t)ybase * WH + x0;
    float* ob1 = out + (size_t)(ybase + 1) * WH + x0;

    uint4 B[4], Bn[4];
#pragma unroll
    for (int ks = 0; ks < 4; ks++) {
        if (ks >= ksteps) break;
        B[ks] = F4[(ks * 4 + lr) * CSTR4 + lq];   // it=0: cb = 0*8 + lq
    }

#pragma unroll
    for (int it = 0; it < 16; it++) {
        // prefetch next iteration's fragments
        if (it < 15) {
            const int cbn = (it + 1) * 8 + lq;
#pragma unroll
            for (int ks = 0; ks < 4; ks++) {
                if (ks >= ksteps) break;
                Bn[ks] = F4[(ks * 4 + lr) * CSTR4 + cbn];
            }
        }

        float acc0[4] = {0.f, 0.f, 0.f, 0.f};
        float acc1[4] = {0.f, 0.f, 0.f, 0.f};
#pragma unroll
        for (int ks = 0; ks < 4; ks++) {
            if (ks >= ksteps) break;
            MMA_BF16(acc0, ah[0][ks][0], ah[0][ks][1], ah[0][ks][2], ah[0][ks][3], B[ks].x, B[ks].y);
            MMA_BF16(acc0, al[0][ks][0], al[0][ks][1], al[0][ks][2], al[0][ks][3], B[ks].x, B[ks].y);
            MMA_BF16(acc0, ah[0][ks][0], ah[0][ks][1], ah[0][ks][2], ah[0][ks][3], B[ks].z, B[ks].w);
            MMA_BF16(acc1, ah[1][ks][0], ah[1][ks][1], ah[1][ks][2], ah[1][ks][3], B[ks].x, B[ks].y);
            MMA_BF16(acc1, al[1][ks][0], al[1][ks][1], al[1][ks][2], al[1][ks][3], B[ks].x, B[ks].y);
            MMA_BF16(acc1, ah[1][ks][0], ah[1][ks][1], ah[1][ks][2], ah[1][ks][3], B[ks].z, B[ks].w);
        }

        const int ch = it * 8 + lr * 2;
        float* o0 = ob0 + (size_t)ch * HW;
        float* o1 = ob1 + (size_t)ch * HW;
        *(float2*)(o0)      = make_float2(acc0[0] * inv[0][0], acc0[2] * inv[0][1]);
        *(float2*)(o0 + HW) = make_float2(acc0[1] * inv[0][0], acc0[3] * inv[0][1]);
        *(float2*)(o1)      = make_float2(acc1[0] * inv[1][0], acc1[2] * inv[1][1]);
        *(float2*)(o1 + HW) = make_float2(acc1[1] * inv[1][0], acc1[3] * inv[1][1]);

#pragma unroll
        for (int ks = 0; ks < 4; ks++) B[ks] = Bn[ks];
    }
}

extern "C" void kernel_launch(void* const* d_in, const int* in_sizes, int n_in,
                              void* d_out, int out_size) {
    const float* feat  = (const float*)d_in[0];
    const float* guide = (const float*)d_in[1];
    const float* sx    = (const float*)d_in[2];
    const float* sy    = (const float*)d_in[3];
    const float* th    = (const float*)d_in[4];
    const float* sr    = (const float*)d_in[5];
    float* out = (float*)d_out;

    cudaFuncSetAttribute(jbu_main_kernel,
                         cudaFuncAttributeMaxDynamicSharedMemorySize, SMEM_BYTES);

    jbu_prep_kernel<<<512, 256>>>(feat, guide);
    dim3 grid(WL, HL, 2);
    jbu_main_kernel<<<grid, 128, SMEM_BYTES>>>(guide, sx, sy, th, sr, out);
}